// round 8
// baseline (speedup 1.0000x reference)
#include <cuda_runtime.h>
#include <cuda_bf16.h>
#include <cstdint>

#define NN 100000
#define NE 1600000
#define NG 1024
#define DD 128
#define NB_SCAN 391   // ceil(NN/256)

// ---------------- scratch (device globals; zero-initialized at load; every call
// re-zeros deg/cursor/pool in k_final's tail so replays see identical state) ----
__device__ float g_agg[NN * DD];
__device__ float g_h1[NN * DD];
__device__ float g_h2[NN * DD];
__device__ __nv_bfloat16 g_xb[NN * DD];   // bf16 gather source (x, then h1)
__device__ float g_pool[NG * DD];
// W in fragment order: [layer][j(n-tile 0..15)][s(k-step 0..15)][lane 0..31] -> uint2
__device__ uint2 g_WfH[2 * 16 * 16 * 32];
__device__ uint2 g_WfL[2 * 16 * 16 * 32];
__device__ int   g_deg[NN];
__device__ int   g_rowptr[NN + 1];
__device__ int   g_cursor[NN];
__device__ int   g_esrc[NE];
__device__ int   g_bsum[512];
__device__ int   g_boff[512];

// ---------------- helpers ----------------
__device__ __forceinline__ uint32_t smem_to_u32(const void* p) {
    uint32_t a;
    asm("{ .reg .u64 t; cvta.to.shared.u64 t, %1; cvt.u32.u64 %0, t; }" : "=r"(a) : "l"(p));
    return a;
}
__device__ __forceinline__ uint32_t bf2u(__nv_bfloat162 v) { return *reinterpret_cast<uint32_t*>(&v); }

#define LDM_X4(r, addr) \
    asm volatile("ldmatrix.sync.aligned.m8n8.x4.shared.b16 {%0,%1,%2,%3}, [%4];" \
        : "=r"((r)[0]), "=r"((r)[1]), "=r"((r)[2]), "=r"((r)[3]) : "r"(addr))

#define MMA_BF16(c, a, b) \
    asm volatile("mma.sync.aligned.m16n8k16.row.col.f32.bf16.bf16.f32 " \
        "{%0,%1,%2,%3}, {%4,%5,%6,%7}, {%8,%9}, {%0,%1,%2,%3};" \
        : "+f"((c)[0]), "+f"((c)[1]), "+f"((c)[2]), "+f"((c)[3]) \
        : "r"((a)[0]), "r"((a)[1]), "r"((a)[2]), "r"((a)[3]), "r"((b).x), "r"((b).y))

// ---------------- prep: x->bf16 copy + weight frag split (fused) ----------------
#define PREP_XB_BLKS 12500   // NN*DD/4 / 256
__global__ void k_prep(const float* __restrict__ x,
                       const float* __restrict__ W1l, const float* __restrict__ W1r,
                       const float* __restrict__ W2l, const float* __restrict__ W2r) {
    if (blockIdx.x < PREP_XB_BLKS) {
        int i = blockIdx.x * 256 + threadIdx.x;
        float4 f = ((const float4*)x)[i];
        __nv_bfloat162 a = __floats2bfloat162_rn(f.x, f.y);
        __nv_bfloat162 b = __floats2bfloat162_rn(f.z, f.w);
        ((uint2*)g_xb)[i] = make_uint2(bf2u(a), bf2u(b));
        return;
    }
    int i = (blockIdx.x - PREP_XB_BLKS) * 256 + threadIdx.x;   // 0 .. 16383
    if (i >= 2 * 16 * 16 * 32) return;
    int lane = i & 31;
    int s = (i >> 5) & 15;
    int j = (i >> 9) & 15;
    int layer = i >> 13;
    int n = j * 8 + (lane >> 2);
    int k = s * 16 + (lane & 3) * 2;
    const float* Wl = layer ? W2l : W1l;
    const float* Wr = layer ? W2r : W1r;
    float w[4];
#pragma unroll
    for (int q = 0; q < 4; q++) {
        int kk = k + (q >> 1) * 8 + (q & 1);
        w[q] = (kk < DD) ? Wl[n * DD + kk] : Wr[n * DD + (kk - DD)];
    }
    __nv_bfloat16 h[4], l[4];
#pragma unroll
    for (int q = 0; q < 4; q++) {
        h[q] = __float2bfloat16(w[q]);
        l[q] = __float2bfloat16(w[q] - __bfloat162float(h[q]));
    }
    __nv_bfloat162 h01; h01.x = h[0]; h01.y = h[1];
    __nv_bfloat162 h23; h23.x = h[2]; h23.y = h[3];
    __nv_bfloat162 l01; l01.x = l[0]; l01.y = l[1];
    __nv_bfloat162 l23; l23.x = l[2]; l23.y = l[3];
    g_WfH[i] = make_uint2(bf2u(h01), bf2u(h23));
    g_WfL[i] = make_uint2(bf2u(l01), bf2u(l23));
}

// ---------------- CSR build (edge_index is int32: JAX x64 disabled) ----------------
__global__ void k_deg(const int* __restrict__ dst) {
    int i = blockIdx.x * blockDim.x + threadIdx.x;
    if (i < NE) atomicAdd(&g_deg[dst[i]], 1);
}

__global__ void k_scanA() {
    __shared__ int s[256];
    int b = blockIdx.x, t = threadIdx.x;
    int i = b * 256 + t;
    int v = (i < NN) ? g_deg[i] : 0;
    s[t] = v;
    __syncthreads();
#pragma unroll
    for (int off = 1; off < 256; off <<= 1) {
        int add = (t >= off) ? s[t - off] : 0;
        __syncthreads();
        s[t] += add;
        __syncthreads();
    }
    if (i < NN) g_rowptr[i] = s[t] - v;
    if (t == 255) g_bsum[b] = s[255];
}

__global__ void k_scanB() {
    __shared__ int s[512];
    int t = threadIdx.x;
    int v = (t < NB_SCAN) ? g_bsum[t] : 0;
    s[t] = v;
    __syncthreads();
#pragma unroll
    for (int off = 1; off < 512; off <<= 1) {
        int add = (t >= off) ? s[t - off] : 0;
        __syncthreads();
        s[t] += add;
        __syncthreads();
    }
    if (t < NB_SCAN) g_boff[t] = s[t] - v;
}

__global__ void k_scanC() {
    int i = blockIdx.x * blockDim.x + threadIdx.x;
    if (i < NN) g_rowptr[i] += g_boff[i >> 8];
    if (i == 0) g_rowptr[NN] = NE;
}

__global__ void k_scatter(const int* __restrict__ src, const int* __restrict__ dst) {
    int i = blockIdx.x * blockDim.x + threadIdx.x;
    if (i >= NE) return;
    int d = dst[i];
    int pos = atomicAdd(&g_cursor[d], 1);
    g_esrc[g_rowptr[d] + pos] = src[i];
}

// ---------------- mean aggregation: warp per node, deep MLP ----------------
// 32 edge indices fetched per coalesced LDG + shfl broadcast; 8 gathers in flight.
__global__ void k_agg(float* __restrict__ out) {
    int w = (blockIdx.x * blockDim.x + threadIdx.x) >> 5;
    int lane = threadIdx.x & 31;
    if (w >= NN) return;
    int beg = g_rowptr[w], end = g_rowptr[w + 1];
    const uint2* in2 = (const uint2*)g_xb;
    float a0 = 0.f, a1 = 0.f, a2 = 0.f, a3 = 0.f;
#pragma unroll 1
    for (int base = beg; base < end; base += 32) {
        int rem = end - base;
        int idx = 0;
        if (lane < rem) idx = __ldg(&g_esrc[base + lane]);
        int cnt = rem < 32 ? rem : 32;
#pragma unroll 1
        for (int j = 0; j < cnt; j += 8) {
            int lim = cnt - j;
            uint2 v[8];
#pragma unroll
            for (int q = 0; q < 8; q++) {
                int s = __shfl_sync(0xffffffffu, idx, (j + q) & 31);
                v[q] = (q < lim) ? __ldg(&in2[(size_t)s * 32 + lane])
                                 : make_uint2(0u, 0u);   // bf16 zeros
            }
#pragma unroll
            for (int q = 0; q < 8; q++) {
                float2 p0 = __bfloat1622float2(*(__nv_bfloat162*)&v[q].x);
                float2 p1 = __bfloat1622float2(*(__nv_bfloat162*)&v[q].y);
                a0 += p0.x; a1 += p0.y; a2 += p1.x; a3 += p1.y;
            }
        }
    }
    float inv = (end > beg) ? 1.0f / (float)(end - beg) : 0.0f;
    float4 r; r.x = a0 * inv; r.y = a1 * inv; r.z = a2 * inv; r.w = a3 * inv;
    ((float4*)out)[w * 32 + lane] = r;
}

// ---------------- mma.sync SAGE GEMM (unchanged from R5/R7) ----------------
#define SA_STRIDE 72   // bf16 elems per row (144B), conflict-free ldmatrix
__global__ void __launch_bounds__(256, 2)
k_gemm_mma(const float* __restrict__ Ag, const float* __restrict__ Bx,
           const uint2* __restrict__ WfH, const uint2* __restrict__ WfL,
           const float* __restrict__ bias, float* __restrict__ out,
           __nv_bfloat16* __restrict__ outb) {
    __shared__ __nv_bfloat16 sAh[128 * SA_STRIDE];
    __shared__ __nv_bfloat16 sAl[128 * SA_STRIDE];
    int tid = threadIdx.x;
    int wid = tid >> 5, lane = tid & 31;
    int m0 = blockIdx.x * 128;
    int wm = wid & 3, wn = wid >> 2;

    float acc[2][8][4];
#pragma unroll
    for (int a = 0; a < 2; a++)
#pragma unroll
        for (int b = 0; b < 8; b++)
#pragma unroll
            for (int q = 0; q < 4; q++) acc[a][b][q] = 0.f;

    int frow = tid >> 1, fhalf = tid & 1;
    bool okrow = (m0 + frow) < NN;

    int g = lane >> 3, ri = lane & 7;
    uint32_t sAh_u = smem_to_u32(sAh);
    uint32_t sAl_u = smem_to_u32(sAl);

#pragma unroll 1
    for (int c = 0; c < 4; c++) {
        const float* srcm = (c < 2) ? Ag : Bx;
        int kcol = (c & 1) * 64;
        const float4* sp = (const float4*)(srcm + (size_t)(m0 + frow) * DD + kcol + fhalf * 32);
        uint32_t dst_off = (uint32_t)frow * SA_STRIDE + (uint32_t)fhalf * 32;
#pragma unroll
        for (int q = 0; q < 8; q++) {
            float4 f;
            if (okrow) f = sp[q];
            else f = make_float4(0.f, 0.f, 0.f, 0.f);
            __nv_bfloat162 h01 = __floats2bfloat162_rn(f.x, f.y);
            __nv_bfloat162 h23 = __floats2bfloat162_rn(f.z, f.w);
            __nv_bfloat162 l01 = __floats2bfloat162_rn(f.x - __bfloat162float(h01.x),
                                                       f.y - __bfloat162float(h01.y));
            __nv_bfloat162 l23 = __floats2bfloat162_rn(f.z - __bfloat162float(h23.x),
                                                       f.w - __bfloat162float(h23.y));
            *(uint2*)(sAh + dst_off + q * 4) = make_uint2(bf2u(h01), bf2u(h23));
            *(uint2*)(sAl + dst_off + q * 4) = make_uint2(bf2u(l01), bf2u(l23));
        }
        __syncthreads();

#pragma unroll
        for (int ss = 0; ss < 4; ss++) {
            int s = c * 4 + ss;
            int k0 = ss * 16;
            uint32_t Ah[2][4], Al[2][4];
#pragma unroll
            for (int mt = 0; mt < 2; mt++) {
                uint32_t row = (uint32_t)(wm * 32 + mt * 16 + (g & 1) * 8 + ri);
                uint32_t byo = (row * SA_STRIDE + (uint32_t)(k0 + (g >> 1) * 8)) * 2;
                LDM_X4(Ah[mt], sAh_u + byo);
                LDM_X4(Al[mt], sAl_u + byo);
            }
#pragma unroll
            for (int nt = 0; nt < 8; nt++) {
                int idx = (((wn * 8 + nt) * 16 + s) << 5) + lane;
                uint2 bh = __ldg(&WfH[idx]);
                uint2 bl = __ldg(&WfL[idx]);
                MMA_BF16(acc[0][nt], Ah[0], bh);
                MMA_BF16(acc[1][nt], Ah[1], bh);
                MMA_BF16(acc[0][nt], Al[0], bh);
                MMA_BF16(acc[1][nt], Al[1], bh);
                MMA_BF16(acc[0][nt], Ah[0], bl);
                MMA_BF16(acc[1][nt], Ah[1], bl);
            }
        }
        __syncthreads();
    }

    int r_in = lane >> 2;
    int n_in = (lane & 3) * 2;
#pragma unroll
    for (int nt = 0; nt < 8; nt++) {
        int n = wn * 64 + nt * 8 + n_in;
        float2 bb = *(const float2*)(bias + n);
#pragma unroll
        for (int mt = 0; mt < 2; mt++) {
            int r0 = m0 + wm * 32 + mt * 16 + r_in;
            if (r0 < NN) {
                float2 o;
                o.x = fmaxf(acc[mt][nt][0] + bb.x, 0.f);
                o.y = fmaxf(acc[mt][nt][1] + bb.y, 0.f);
                *(float2*)(out + (size_t)r0 * DD + n) = o;
                if (outb) {
                    __nv_bfloat162 ob = __floats2bfloat162_rn(o.x, o.y);
                    *(uint32_t*)(outb + (size_t)r0 * DD + n) = bf2u(ob);
                }
            }
            int r1 = r0 + 8;
            if (r1 < NN) {
                float2 o;
                o.x = fmaxf(acc[mt][nt][2] + bb.x, 0.f);
                o.y = fmaxf(acc[mt][nt][3] + bb.y, 0.f);
                *(float2*)(out + (size_t)r1 * DD + n) = o;
                if (outb) {
                    __nv_bfloat162 ob = __floats2bfloat162_rn(o.x, o.y);
                    *(uint32_t*)(outb + (size_t)r1 * DD + n) = bf2u(ob);
                }
            }
        }
    }
}

// ---------------- global add pool (batch is sorted, int32) ----------------
#define NPB 256
__global__ void k_pool(const float* __restrict__ h, const int* __restrict__ batch) {
    int t = threadIdx.x;
    int start = blockIdx.x * NPB;
    int end = start + NPB; if (end > NN) end = NN;
    if (start >= NN) return;
    int cur = batch[start];
    float sum = 0.f;
    for (int i = start; i < end; i++) {
        int b = __ldg(&batch[i]);
        if (b != cur) {
            atomicAdd(&g_pool[cur * DD + t], sum);
            sum = 0.f; cur = b;
        }
        sum += h[(size_t)i * DD + t];
    }
    atomicAdd(&g_pool[cur * DD + t], sum);
}

// ---------------- LayerNorm + final linear + scratch re-zero for next replay ----
__global__ void k_final(const float* __restrict__ ln_g, const float* __restrict__ ln_b,
                        const float* __restrict__ Wlin, const float* __restrict__ blin,
                        float* __restrict__ out) {
    int gtid = blockIdx.x * blockDim.x + threadIdx.x;
    int w = gtid >> 5;
    int lane = threadIdx.x & 31;
    if (w < NG) {
        float4 v = ((const float4*)g_pool)[w * 32 + lane];
        float s = v.x + v.y + v.z + v.w;
#pragma unroll
        for (int o = 16; o; o >>= 1) s += __shfl_xor_sync(0xffffffffu, s, o);
        float mean = s * (1.0f / 128.0f);
        float dx = v.x - mean, dy = v.y - mean, dz = v.z - mean, dw = v.w - mean;
        float q = dx * dx + dy * dy + dz * dz + dw * dw;
#pragma unroll
        for (int o = 16; o; o >>= 1) q += __shfl_xor_sync(0xffffffffu, q, o);
        float var = q * (1.0f / 128.0f);
        float r = rsqrtf(var + 1e-5f);
        float4 gg = ((const float4*)ln_g)[lane];
        float4 bb = ((const float4*)ln_b)[lane];
        float n0 = dx * r * gg.x + bb.x;
        float n1 = dy * r * gg.y + bb.y;
        float n2 = dz * r * gg.z + bb.z;
        float n3 = dw * r * gg.w + bb.w;
        float4 w0 = ((const float4*)Wlin)[lane];
        float4 w1 = ((const float4*)Wlin)[32 + lane];
        float d0 = n0 * w0.x + n1 * w0.y + n2 * w0.z + n3 * w0.w;
        float d1 = n0 * w1.x + n1 * w1.y + n2 * w1.z + n3 * w1.w;
#pragma unroll
        for (int o = 16; o; o >>= 1) {
            d0 += __shfl_xor_sync(0xffffffffu, d0, o);
            d1 += __shfl_xor_sync(0xffffffffu, d1, o);
        }
        if (lane == 0) {
            out[w * 2 + 0] = d0 + blin[0];
            out[w * 2 + 1] = d1 + blin[1];
        }
        // this warp is the only reader of g_pool[w] -> race-free re-zero
        ((float4*)g_pool)[w * 32 + lane] = make_float4(0.f, 0.f, 0.f, 0.f);
    }
    // re-zero deg/cursor for next replay (NG*32 = 32768 threads total)
    for (int i = gtid; i < NN; i += NG * 32) { g_deg[i] = 0; g_cursor[i] = 0; }
}

// ---------------- launch ----------------
extern "C" void kernel_launch(void* const* d_in, const int* in_sizes, int n_in,
                              void* d_out, int out_size) {
    const float* x     = (const float*)d_in[0];
    const int*   ei    = (const int*)d_in[1];
    const int*   bat   = (const int*)d_in[2];
    const float* W1l   = (const float*)d_in[3];
    const float* b1l   = (const float*)d_in[4];
    const float* W1r   = (const float*)d_in[5];
    const float* W2l   = (const float*)d_in[6];
    const float* b2l   = (const float*)d_in[7];
    const float* W2r   = (const float*)d_in[8];
    const float* ln_g  = (const float*)d_in[9];
    const float* ln_b  = (const float*)d_in[10];
    const float* Wlin  = (const float*)d_in[11];
    const float* blin  = (const float*)d_in[12];

    const int* src = ei;
    const int* dst = ei + NE;

    float *agg, *h1, *h2;
    __nv_bfloat16* xb;
    uint2 *wfh, *wfl;
    cudaGetSymbolAddress((void**)&agg, g_agg);
    cudaGetSymbolAddress((void**)&h1,  g_h1);
    cudaGetSymbolAddress((void**)&h2,  g_h2);
    cudaGetSymbolAddress((void**)&xb,  g_xb);
    cudaGetSymbolAddress((void**)&wfh, g_WfH);
    cudaGetSymbolAddress((void**)&wfl, g_WfL);

    k_prep<<<PREP_XB_BLKS + 64, 256>>>(x, W1l, W1r, W2l, W2r);
    k_deg<<<(NE + 255) / 256, 256>>>(dst);
    k_scanA<<<NB_SCAN, 256>>>();
    k_scanB<<<1, 512>>>();
    k_scanC<<<NB_SCAN + 1, 256>>>();
    k_scatter<<<(NE + 255) / 256, 256>>>(src, dst);

    int nblk = (NN + 127) / 128;
    const int LSTRIDE = 16 * 16 * 32;   // per-layer frag stride
    // layer 1  (agg from bf16(x); GEMM writes h1 fp32 + bf16 plane for layer-2 gather)
    k_agg<<<(NN * 32 + 255) / 256, 256>>>(agg);
    k_gemm_mma<<<nblk, 256>>>(agg, x, wfh, wfl, b1l, h1, xb);
    // layer 2
    k_agg<<<(NN * 32 + 255) / 256, 256>>>(agg);
    k_gemm_mma<<<nblk, 256>>>(agg, h1, wfh + LSTRIDE, wfl + LSTRIDE, b2l, h2, (__nv_bfloat16*)nullptr);

    k_pool<<<(NN + NPB - 1) / NPB, 128>>>(h2, bat);
    k_final<<<(NG * 32 + 255) / 256, 256>>>(ln_g, ln_b, Wlin, blin, (float*)d_out);
}

// round 9
// speedup vs baseline: 1.1002x; 1.1002x over previous
#include <cuda_runtime.h>
#include <cuda_bf16.h>
#include <cstdint>

#define NN 100000
#define NE 1600000
#define NG 1024
#define DD 128
#define NB_SCAN 391   // ceil(NN/256)

// ---------------- scratch (device globals; zero-initialized at load; every call
// re-zeros deg/cursor/pool/alloc in k_final's tail so replays see identical state)
__device__ float g_agg[NN * DD];
__device__ float g_h1[NN * DD];
__device__ float g_h2[NN * DD];
__device__ __nv_bfloat16 g_xb[NN * DD];   // bf16 gather source (x, then h1)
__device__ float g_pool[NG * DD];
// W in fragment order: [layer][j(n-tile 0..15)][s(k-step 0..15)][lane 0..31] -> uint2
__device__ uint2 g_WfH[2 * 16 * 16 * 32];
__device__ uint2 g_WfL[2 * 16 * 16 * 32];
__device__ int   g_deg[NN];
__device__ int   g_rowptr[NN];      // allocated bucket start (NOT sorted prefix)
__device__ int   g_cursor[NN];
__device__ int   g_esrc[NE];
__device__ int   g_alloc;           // bump allocator for buckets

// ---------------- helpers ----------------
__device__ __forceinline__ uint32_t smem_to_u32(const void* p) {
    uint32_t a;
    asm("{ .reg .u64 t; cvta.to.shared.u64 t, %1; cvt.u32.u64 %0, t; }" : "=r"(a) : "l"(p));
    return a;
}
__device__ __forceinline__ uint32_t bf2u(__nv_bfloat162 v) { return *reinterpret_cast<uint32_t*>(&v); }

#define LDM_X4(r, addr) \
    asm volatile("ldmatrix.sync.aligned.m8n8.x4.shared.b16 {%0,%1,%2,%3}, [%4];" \
        : "=r"((r)[0]), "=r"((r)[1]), "=r"((r)[2]), "=r"((r)[3]) : "r"(addr))

#define MMA_BF16(c, a, b) \
    asm volatile("mma.sync.aligned.m16n8k16.row.col.f32.bf16.bf16.f32 " \
        "{%0,%1,%2,%3}, {%4,%5,%6,%7}, {%8,%9}, {%0,%1,%2,%3};" \
        : "+f"((c)[0]), "+f"((c)[1]), "+f"((c)[2]), "+f"((c)[3]) \
        : "r"((a)[0]), "r"((a)[1]), "r"((a)[2]), "r"((a)[3]), "r"((b).x), "r"((b).y))

// ---------------- slot 0: prep (x->bf16, W frag split) + degree count ----------------
#define PREP_XB_BLKS 12500   // NN*DD/4 / 256
#define PREP_WF_BLKS 64
__global__ void k_prep_deg(const float* __restrict__ x,
                           const float* __restrict__ W1l, const float* __restrict__ W1r,
                           const float* __restrict__ W2l, const float* __restrict__ W2r,
                           const int* __restrict__ dst) {
    if (blockIdx.x < PREP_XB_BLKS) {
        int i = blockIdx.x * 256 + threadIdx.x;
        float4 f = ((const float4*)x)[i];
        __nv_bfloat162 a = __floats2bfloat162_rn(f.x, f.y);
        __nv_bfloat162 b = __floats2bfloat162_rn(f.z, f.w);
        ((uint2*)g_xb)[i] = make_uint2(bf2u(a), bf2u(b));
        return;
    }
    if (blockIdx.x < PREP_XB_BLKS + PREP_WF_BLKS) {
        int i = (blockIdx.x - PREP_XB_BLKS) * 256 + threadIdx.x;   // 0 .. 16383
        if (i >= 2 * 16 * 16 * 32) return;
        int lane = i & 31;
        int s = (i >> 5) & 15;
        int j = (i >> 9) & 15;
        int layer = i >> 13;
        int n = j * 8 + (lane >> 2);
        int k = s * 16 + (lane & 3) * 2;
        const float* Wl = layer ? W2l : W1l;
        const float* Wr = layer ? W2r : W1r;
        float w[4];
#pragma unroll
        for (int q = 0; q < 4; q++) {
            int kk = k + (q >> 1) * 8 + (q & 1);
            w[q] = (kk < DD) ? Wl[n * DD + kk] : Wr[n * DD + (kk - DD)];
        }
        __nv_bfloat16 h[4], l[4];
#pragma unroll
        for (int q = 0; q < 4; q++) {
            h[q] = __float2bfloat16(w[q]);
            l[q] = __float2bfloat16(w[q] - __bfloat162float(h[q]));
        }
        __nv_bfloat162 h01; h01.x = h[0]; h01.y = h[1];
        __nv_bfloat162 h23; h23.x = h[2]; h23.y = h[3];
        __nv_bfloat162 l01; l01.x = l[0]; l01.y = l[1];
        __nv_bfloat162 l23; l23.x = l[2]; l23.y = l[3];
        g_WfH[i] = make_uint2(bf2u(h01), bf2u(h23));
        g_WfL[i] = make_uint2(bf2u(l01), bf2u(l23));
        return;
    }
    int i = (blockIdx.x - PREP_XB_BLKS - PREP_WF_BLKS) * 256 + threadIdx.x;
    if (i < NE) atomicAdd(&g_deg[dst[i]], 1);
}

// ---------------- slot 1: bucket allocation (local scan + one atomic per block) ----
__global__ void k_alloc() {
    __shared__ int s[256];
    __shared__ int base;
    int b = blockIdx.x, t = threadIdx.x;
    int i = b * 256 + t;
    int v = (i < NN) ? g_deg[i] : 0;
    s[t] = v;
    __syncthreads();
#pragma unroll
    for (int off = 1; off < 256; off <<= 1) {
        int add = (t >= off) ? s[t - off] : 0;
        __syncthreads();
        s[t] += add;
        __syncthreads();
    }
    if (t == 255) base = atomicAdd(&g_alloc, s[255]);
    __syncthreads();
    if (i < NN) g_rowptr[i] = base + s[t] - v;
}

// ---------------- slot 2: scatter edges into buckets ----------------
__global__ void k_scatter(const int* __restrict__ src, const int* __restrict__ dst) {
    int i = blockIdx.x * blockDim.x + threadIdx.x;
    if (i >= NE) return;
    int d = dst[i];
    int pos = atomicAdd(&g_cursor[d], 1);
    g_esrc[g_rowptr[d] + pos] = src[i];
}

// ---------------- slot 3 (PROFILED): mean aggregation, warp per node ----------------
// 8 independent index-load + gather pairs in flight; bf16 source, fp32 accum.
__global__ void k_agg(float* __restrict__ out) {
    int w = (blockIdx.x * blockDim.x + threadIdx.x) >> 5;
    int lane = threadIdx.x & 31;
    if (w >= NN) return;
    int beg = g_rowptr[w];
    int dcnt = g_deg[w];
    int end = beg + dcnt;
    const uint2* in2 = (const uint2*)g_xb;
    float a0 = 0.f, a1 = 0.f, a2 = 0.f, a3 = 0.f;
    int e = beg;
#pragma unroll 1
    for (; e + 7 < end; e += 8) {
        int s0 = __ldg(&g_esrc[e]);
        int s1 = __ldg(&g_esrc[e + 1]);
        int s2 = __ldg(&g_esrc[e + 2]);
        int s3 = __ldg(&g_esrc[e + 3]);
        int s4 = __ldg(&g_esrc[e + 4]);
        int s5 = __ldg(&g_esrc[e + 5]);
        int s6 = __ldg(&g_esrc[e + 6]);
        int s7 = __ldg(&g_esrc[e + 7]);
        uint2 v0 = __ldg(&in2[(size_t)s0 * 32 + lane]);
        uint2 v1 = __ldg(&in2[(size_t)s1 * 32 + lane]);
        uint2 v2 = __ldg(&in2[(size_t)s2 * 32 + lane]);
        uint2 v3 = __ldg(&in2[(size_t)s3 * 32 + lane]);
        uint2 v4 = __ldg(&in2[(size_t)s4 * 32 + lane]);
        uint2 v5 = __ldg(&in2[(size_t)s5 * 32 + lane]);
        uint2 v6 = __ldg(&in2[(size_t)s6 * 32 + lane]);
        uint2 v7 = __ldg(&in2[(size_t)s7 * 32 + lane]);
#pragma unroll
        for (int q = 0; q < 8; q++) {
            uint2 v = q == 0 ? v0 : q == 1 ? v1 : q == 2 ? v2 : q == 3 ? v3
                    : q == 4 ? v4 : q == 5 ? v5 : q == 6 ? v6 : v7;
            float2 p0 = __bfloat1622float2(*(__nv_bfloat162*)&v.x);
            float2 p1 = __bfloat1622float2(*(__nv_bfloat162*)&v.y);
            a0 += p0.x; a1 += p0.y; a2 += p1.x; a3 += p1.y;
        }
    }
    for (; e < end; e++) {
        int s0 = __ldg(&g_esrc[e]);
        uint2 v = __ldg(&in2[(size_t)s0 * 32 + lane]);
        float2 p0 = __bfloat1622float2(*(__nv_bfloat162*)&v.x);
        float2 p1 = __bfloat1622float2(*(__nv_bfloat162*)&v.y);
        a0 += p0.x; a1 += p0.y; a2 += p1.x; a3 += p1.y;
    }
    float inv = (dcnt > 0) ? 1.0f / (float)dcnt : 0.0f;
    float4 r; r.x = a0 * inv; r.y = a1 * inv; r.z = a2 * inv; r.w = a3 * inv;
    ((float4*)out)[w * 32 + lane] = r;
}

// ---------------- mma.sync SAGE GEMM (unchanged, proven) ----------------
#define SA_STRIDE 72   // bf16 elems per row (144B), conflict-free ldmatrix
__global__ void __launch_bounds__(256, 2)
k_gemm_mma(const float* __restrict__ Ag, const float* __restrict__ Bx,
           const uint2* __restrict__ WfH, const uint2* __restrict__ WfL,
           const float* __restrict__ bias, float* __restrict__ out,
           __nv_bfloat16* __restrict__ outb) {
    __shared__ __nv_bfloat16 sAh[128 * SA_STRIDE];
    __shared__ __nv_bfloat16 sAl[128 * SA_STRIDE];
    int tid = threadIdx.x;
    int wid = tid >> 5, lane = tid & 31;
    int m0 = blockIdx.x * 128;
    int wm = wid & 3, wn = wid >> 2;

    float acc[2][8][4];
#pragma unroll
    for (int a = 0; a < 2; a++)
#pragma unroll
        for (int b = 0; b < 8; b++)
#pragma unroll
            for (int q = 0; q < 4; q++) acc[a][b][q] = 0.f;

    int frow = tid >> 1, fhalf = tid & 1;
    bool okrow = (m0 + frow) < NN;

    int g = lane >> 3, ri = lane & 7;
    uint32_t sAh_u = smem_to_u32(sAh);
    uint32_t sAl_u = smem_to_u32(sAl);

#pragma unroll 1
    for (int c = 0; c < 4; c++) {
        const float* srcm = (c < 2) ? Ag : Bx;
        int kcol = (c & 1) * 64;
        const float4* sp = (const float4*)(srcm + (size_t)(m0 + frow) * DD + kcol + fhalf * 32);
        uint32_t dst_off = (uint32_t)frow * SA_STRIDE + (uint32_t)fhalf * 32;
#pragma unroll
        for (int q = 0; q < 8; q++) {
            float4 f;
            if (okrow) f = sp[q];
            else f = make_float4(0.f, 0.f, 0.f, 0.f);
            __nv_bfloat162 h01 = __floats2bfloat162_rn(f.x, f.y);
            __nv_bfloat162 h23 = __floats2bfloat162_rn(f.z, f.w);
            __nv_bfloat162 l01 = __floats2bfloat162_rn(f.x - __bfloat162float(h01.x),
                                                       f.y - __bfloat162float(h01.y));
            __nv_bfloat162 l23 = __floats2bfloat162_rn(f.z - __bfloat162float(h23.x),
                                                       f.w - __bfloat162float(h23.y));
            *(uint2*)(sAh + dst_off + q * 4) = make_uint2(bf2u(h01), bf2u(h23));
            *(uint2*)(sAl + dst_off + q * 4) = make_uint2(bf2u(l01), bf2u(l23));
        }
        __syncthreads();

#pragma unroll
        for (int ss = 0; ss < 4; ss++) {
            int s = c * 4 + ss;
            int k0 = ss * 16;
            uint32_t Ah[2][4], Al[2][4];
#pragma unroll
            for (int mt = 0; mt < 2; mt++) {
                uint32_t row = (uint32_t)(wm * 32 + mt * 16 + (g & 1) * 8 + ri);
                uint32_t byo = (row * SA_STRIDE + (uint32_t)(k0 + (g >> 1) * 8)) * 2;
                LDM_X4(Ah[mt], sAh_u + byo);
                LDM_X4(Al[mt], sAl_u + byo);
            }
#pragma unroll
            for (int nt = 0; nt < 8; nt++) {
                int idx = (((wn * 8 + nt) * 16 + s) << 5) + lane;
                uint2 bh = __ldg(&WfH[idx]);
                uint2 bl = __ldg(&WfL[idx]);
                MMA_BF16(acc[0][nt], Ah[0], bh);
                MMA_BF16(acc[1][nt], Ah[1], bh);
                MMA_BF16(acc[0][nt], Al[0], bh);
                MMA_BF16(acc[1][nt], Al[1], bh);
                MMA_BF16(acc[0][nt], Ah[0], bl);
                MMA_BF16(acc[1][nt], Ah[1], bl);
            }
        }
        __syncthreads();
    }

    int r_in = lane >> 2;
    int n_in = (lane & 3) * 2;
#pragma unroll
    for (int nt = 0; nt < 8; nt++) {
        int n = wn * 64 + nt * 8 + n_in;
        float2 bb = *(const float2*)(bias + n);
#pragma unroll
        for (int mt = 0; mt < 2; mt++) {
            int r0 = m0 + wm * 32 + mt * 16 + r_in;
            if (r0 < NN) {
                float2 o;
                o.x = fmaxf(acc[mt][nt][0] + bb.x, 0.f);
                o.y = fmaxf(acc[mt][nt][1] + bb.y, 0.f);
                *(float2*)(out + (size_t)r0 * DD + n) = o;
                if (outb) {
                    __nv_bfloat162 ob = __floats2bfloat162_rn(o.x, o.y);
                    *(uint32_t*)(outb + (size_t)r0 * DD + n) = bf2u(ob);
                }
            }
            int r1 = r0 + 8;
            if (r1 < NN) {
                float2 o;
                o.x = fmaxf(acc[mt][nt][2] + bb.x, 0.f);
                o.y = fmaxf(acc[mt][nt][3] + bb.y, 0.f);
                *(float2*)(out + (size_t)r1 * DD + n) = o;
                if (outb) {
                    __nv_bfloat162 ob = __floats2bfloat162_rn(o.x, o.y);
                    *(uint32_t*)(outb + (size_t)r1 * DD + n) = bf2u(ob);
                }
            }
        }
    }
}

// ---------------- global add pool (batch is sorted, int32) ----------------
#define NPB 256
__global__ void k_pool(const float* __restrict__ h, const int* __restrict__ batch) {
    int t = threadIdx.x;
    int start = blockIdx.x * NPB;
    int end = start + NPB; if (end > NN) end = NN;
    if (start >= NN) return;
    int cur = batch[start];
    float sum = 0.f;
    for (int i = start; i < end; i++) {
        int b = __ldg(&batch[i]);
        if (b != cur) {
            atomicAdd(&g_pool[cur * DD + t], sum);
            sum = 0.f; cur = b;
        }
        sum += h[(size_t)i * DD + t];
    }
    atomicAdd(&g_pool[cur * DD + t], sum);
}

// ---------------- LayerNorm + final linear + scratch re-zero for next replay ----
__global__ void k_final(const float* __restrict__ ln_g, const float* __restrict__ ln_b,
                        const float* __restrict__ Wlin, const float* __restrict__ blin,
                        float* __restrict__ out) {
    int gtid = blockIdx.x * blockDim.x + threadIdx.x;
    int w = gtid >> 5;
    int lane = threadIdx.x & 31;
    if (w < NG) {
        float4 v = ((const float4*)g_pool)[w * 32 + lane];
        float s = v.x + v.y + v.z + v.w;
#pragma unroll
        for (int o = 16; o; o >>= 1) s += __shfl_xor_sync(0xffffffffu, s, o);
        float mean = s * (1.0f / 128.0f);
        float dx = v.x - mean, dy = v.y - mean, dz = v.z - mean, dw = v.w - mean;
        float q = dx * dx + dy * dy + dz * dz + dw * dw;
#pragma unroll
        for (int o = 16; o; o >>= 1) q += __shfl_xor_sync(0xffffffffu, q, o);
        float var = q * (1.0f / 128.0f);
        float r = rsqrtf(var + 1e-5f);
        float4 gg = ((const float4*)ln_g)[lane];
        float4 bb = ((const float4*)ln_b)[lane];
        float n0 = dx * r * gg.x + bb.x;
        float n1 = dy * r * gg.y + bb.y;
        float n2 = dz * r * gg.z + bb.z;
        float n3 = dw * r * gg.w + bb.w;
        float4 w0 = ((const float4*)Wlin)[lane];
        float4 w1 = ((const float4*)Wlin)[32 + lane];
        float d0 = n0 * w0.x + n1 * w0.y + n2 * w0.z + n3 * w0.w;
        float d1 = n0 * w1.x + n1 * w1.y + n2 * w1.z + n3 * w1.w;
#pragma unroll
        for (int o = 16; o; o >>= 1) {
            d0 += __shfl_xor_sync(0xffffffffu, d0, o);
            d1 += __shfl_xor_sync(0xffffffffu, d1, o);
        }
        if (lane == 0) {
            out[w * 2 + 0] = d0 + blin[0];
            out[w * 2 + 1] = d1 + blin[1];
        }
        // this warp is the only reader of g_pool[w] -> race-free re-zero
        ((float4*)g_pool)[w * 32 + lane] = make_float4(0.f, 0.f, 0.f, 0.f);
    }
    if (gtid == 0) g_alloc = 0;
    // re-zero deg/cursor for next replay (NG*32 = 32768 threads total)
    for (int i = gtid; i < NN; i += NG * 32) { g_deg[i] = 0; g_cursor[i] = 0; }
}

// ---------------- launch ----------------
extern "C" void kernel_launch(void* const* d_in, const int* in_sizes, int n_in,
                              void* d_out, int out_size) {
    const float* x     = (const float*)d_in[0];
    const int*   ei    = (const int*)d_in[1];
    const int*   bat   = (const int*)d_in[2];
    const float* W1l   = (const float*)d_in[3];
    const float* b1l   = (const float*)d_in[4];
    const float* W1r   = (const float*)d_in[5];
    const float* W2l   = (const float*)d_in[6];
    const float* b2l   = (const float*)d_in[7];
    const float* W2r   = (const float*)d_in[8];
    const float* ln_g  = (const float*)d_in[9];
    const float* ln_b  = (const float*)d_in[10];
    const float* Wlin  = (const float*)d_in[11];
    const float* blin  = (const float*)d_in[12];

    const int* src = ei;
    const int* dst = ei + NE;

    float *agg, *h1, *h2;
    __nv_bfloat16* xb;
    uint2 *wfh, *wfl;
    cudaGetSymbolAddress((void**)&agg, g_agg);
    cudaGetSymbolAddress((void**)&h1,  g_h1);
    cudaGetSymbolAddress((void**)&h2,  g_h2);
    cudaGetSymbolAddress((void**)&xb,  g_xb);
    cudaGetSymbolAddress((void**)&wfh, g_WfH);
    cudaGetSymbolAddress((void**)&wfl, g_WfL);

    int degblks = (NE + 255) / 256;
    k_prep_deg<<<PREP_XB_BLKS + PREP_WF_BLKS + degblks, 256>>>(x, W1l, W1r, W2l, W2r, dst);  // 0
    k_alloc<<<NB_SCAN, 256>>>();                                                              // 1
    k_scatter<<<degblks, 256>>>(src, dst);                                                    // 2

    int nblk = (NN + 127) / 128;
    const int LSTRIDE = 16 * 16 * 32;
    k_agg<<<(NN * 32 + 255) / 256, 256>>>(agg);                                               // 3 (profiled)
    k_gemm_mma<<<nblk, 256>>>(agg, x, wfh, wfl, b1l, h1, xb);                                 // 4
    k_agg<<<(NN * 32 + 255) / 256, 256>>>(agg);                                               // 5
    k_gemm_mma<<<nblk, 256>>>(agg, h1, wfh + LSTRIDE, wfl + LSTRIDE, b2l, h2, (__nv_bfloat16*)nullptr); // 6

    k_pool<<<(NN + NPB - 1) / NPB, 128>>>(h2, bat);                                           // 7
    k_final<<<(NG * 32 + 255) / 256, 256>>>(ln_g, ln_b, Wlin, blin, (float*)d_out);           // 8
}